// round 1
// baseline (speedup 1.0000x reference)
#include <cuda_runtime.h>
#include <cuda_fp16.h>
#include <cstdint>

// Problem dims (fixed for this dataset)
#define T_DIM 256
#define H_DIM 4096
#define I_DIM 14336
#define GS 64
#define NG1 (H_DIM / GS)   // 64 groups along H
#define NG2 (I_DIM / GS)   // 224 groups along I

// Tiling
#define BM 128
#define BN 128
#define BK 64              // one quant group per K-chunk
#define SSTR 72            // smem row stride in halves (64 + 8 pad, keeps 16B align, conflict-free)

#define SMEM_GU (3 * BM * SSTR * 2 + 4 * 128 * 4)   // A + B1 + B3 tiles + s1,z1,s3,z3
#define SMEM_DN (2 * BM * SSTR * 2 + 2 * 128 * 4)   // A + B2 tiles + s2,z2

// Scratch (static __device__: allocation-free per harness rules)
__device__ __half g_xh[T_DIM * H_DIM];   // x in fp16
__device__ __half g_hh[T_DIM * I_DIM];   // silu(gate)*up in fp16

__device__ __forceinline__ void mma16816(float* c, const uint32_t* a, uint32_t b0, uint32_t b1) {
    asm volatile(
        "mma.sync.aligned.m16n8k16.row.col.f32.f16.f16.f32 "
        "{%0,%1,%2,%3}, {%4,%5,%6,%7}, {%8,%9}, {%0,%1,%2,%3};\n"
        : "+f"(c[0]), "+f"(c[1]), "+f"(c[2]), "+f"(c[3])
        : "r"(a[0]), "r"(a[1]), "r"(a[2]), "r"(a[3]), "r"(b0), "r"(b1));
}

// ---------------------------------------------------------------------------
// Kernel 0: convert x [256,4096] fp32 -> fp16
// ---------------------------------------------------------------------------
__global__ void cvt_x_kernel(const float* __restrict__ x) {
    int i = (blockIdx.x * blockDim.x + threadIdx.x) * 4;
    float4 v = *(const float4*)(x + i);
    *(__half2*)&g_xh[i]     = __floats2half2_rn(v.x, v.y);
    *(__half2*)&g_xh[i + 2] = __floats2half2_rn(v.z, v.w);
}

// ---------------------------------------------------------------------------
// Kernel 1: fused gate/up GEMM with on-the-fly HQQ dequant.
//   gate[t,i] = x[t,:] . w1[i,:],  up[t,i] = x[t,:] . w3[i,:]
//   h[t,i]    = silu(gate)*up  -> g_hh (fp16)
// Grid: (T/128, I/128), blockIdx.x (t) fastest so the 2 t-tiles of an i-tile
// are co-resident -> weight int32 reads dedup in L2.
// ---------------------------------------------------------------------------
__global__ void __launch_bounds__(512, 1) gemm_gateup(
    const int* __restrict__ w1q, const float* __restrict__ w1s, const float* __restrict__ w1z,
    const int* __restrict__ w3q, const float* __restrict__ w3s, const float* __restrict__ w3z)
{
    extern __shared__ char smem[];
    __half* As  = (__half*)smem;                         // [128][72]
    __half* B1s = (__half*)(smem + BM * SSTR * 2);       // [128][72]
    __half* B3s = (__half*)(smem + 2 * BM * SSTR * 2);   // [128][72]
    float*  s1s = (float*)(smem + 3 * BM * SSTR * 2);
    float*  z1s = s1s + 128;
    float*  s3s = s1s + 256;
    float*  z3s = s1s + 384;

    const int tid  = threadIdx.x;
    const int lane = tid & 31;
    const int wid  = tid >> 5;
    const int wm   = wid & 3;    // 4 warp rows (m)
    const int wn   = wid >> 2;   // 4 warp cols (n)
    const int t0   = blockIdx.x * BM;
    const int i0   = blockIdx.y * BN;

    float acc1[2][4][4];
    float acc3[2][4][4];
#pragma unroll
    for (int mi = 0; mi < 2; mi++)
#pragma unroll
        for (int ni = 0; ni < 4; ni++)
#pragma unroll
            for (int r = 0; r < 4; r++) { acc1[mi][ni][r] = 0.f; acc3[mi][ni][r] = 0.f; }

    const int arow = wm * 32 + (lane >> 2);
    const int acol = (lane & 3) * 2;
    const int brow = wn * 32 + (lane >> 2);

    for (int kc = 0; kc < H_DIM / BK; ++kc) {
        const int k0 = kc * BK;   // group index == kc

        // Per-chunk scales/zeros for the 128 i-rows of this tile (one fp32 each).
        {
            int r = tid & 127;
            const float* src = (tid < 128) ? w1s : (tid < 256) ? w1z : (tid < 384) ? w3s : w3z;
            float*       dst = (tid < 128) ? s1s : (tid < 256) ? z1s : (tid < 384) ? s3s : z3s;
            dst[r] = src[(size_t)(i0 + r) * NG1 + kc];
        }
        __syncthreads();   // scales visible + prev compute done before tile overwrite

        // A tile: 128x64 halves (vec8 loads)
#pragma unroll
        for (int j = 0; j < 2; j++) {
            int v = tid + j * 512;
            int r = v >> 3, c = (v & 7) * 8;
            *(uint4*)(As + r * SSTR + c) =
                *(const uint4*)(g_xh + (size_t)(t0 + r) * H_DIM + k0 + c);
        }
        // B tiles: 128x64 int32 each, dequant to fp16 (q exact in fp16; one rounding)
#pragma unroll
        for (int j = 0; j < 4; j++) {
            int v = tid + j * 512;
            int r = v >> 4, c = (v & 15) * 4;
            {
                int4 q = *(const int4*)(w1q + (size_t)(i0 + r) * H_DIM + k0 + c);
                float s = s1s[r], z = z1s[r];
                *(__half2*)(B1s + r * SSTR + c)     = __floats2half2_rn(((float)q.x - z) * s, ((float)q.y - z) * s);
                *(__half2*)(B1s + r * SSTR + c + 2) = __floats2half2_rn(((float)q.z - z) * s, ((float)q.w - z) * s);
            }
            {
                int4 q = *(const int4*)(w3q + (size_t)(i0 + r) * H_DIM + k0 + c);
                float s = s3s[r], z = z3s[r];
                *(__half2*)(B3s + r * SSTR + c)     = __floats2half2_rn(((float)q.x - z) * s, ((float)q.y - z) * s);
                *(__half2*)(B3s + r * SSTR + c + 2) = __floats2half2_rn(((float)q.z - z) * s, ((float)q.w - z) * s);
            }
        }
        __syncthreads();

        // Compute: 4 k-steps of 16
#pragma unroll
        for (int ks = 0; ks < 4; ks++) {
            const int kb = ks * 16 + acol;
            uint32_t a[2][4];
#pragma unroll
            for (int mi = 0; mi < 2; mi++) {
                const __half* p = As + (arow + mi * 16) * SSTR + kb;
                a[mi][0] = *(const uint32_t*)p;
                a[mi][1] = *(const uint32_t*)(p + 8 * SSTR);
                a[mi][2] = *(const uint32_t*)(p + 8);
                a[mi][3] = *(const uint32_t*)(p + 8 * SSTR + 8);
            }
#pragma unroll
            for (int ni = 0; ni < 4; ni++) {
                const __half* p1 = B1s + (brow + ni * 8) * SSTR + kb;
                uint32_t b0 = *(const uint32_t*)p1;
                uint32_t b1 = *(const uint32_t*)(p1 + 8);
#pragma unroll
                for (int mi = 0; mi < 2; mi++) mma16816(acc1[mi][ni], a[mi], b0, b1);
                const __half* p3 = B3s + (brow + ni * 8) * SSTR + kb;
                b0 = *(const uint32_t*)p3;
                b1 = *(const uint32_t*)(p3 + 8);
#pragma unroll
                for (int mi = 0; mi < 2; mi++) mma16816(acc3[mi][ni], a[mi], b0, b1);
            }
        }
        // next iteration's first __syncthreads guards tile reuse
    }

    // Epilogue: h = silu(gate)*up, fp16 store
#pragma unroll
    for (int mi = 0; mi < 2; mi++) {
#pragma unroll
        for (int ni = 0; ni < 4; ni++) {
            int r0  = t0 + wm * 32 + mi * 16 + (lane >> 2);
            int col = i0 + wn * 32 + ni * 8 + (lane & 3) * 2;
            float g0 = acc1[mi][ni][0], g1 = acc1[mi][ni][1];
            float g2 = acc1[mi][ni][2], g3 = acc1[mi][ni][3];
            float u0 = acc3[mi][ni][0], u1 = acc3[mi][ni][1];
            float u2 = acc3[mi][ni][2], u3 = acc3[mi][ni][3];
            float h0 = g0 / (1.f + __expf(-g0)) * u0;
            float h1 = g1 / (1.f + __expf(-g1)) * u1;
            float h2 = g2 / (1.f + __expf(-g2)) * u2;
            float h3 = g3 / (1.f + __expf(-g3)) * u3;
            *(__half2*)&g_hh[(size_t)r0 * I_DIM + col]       = __floats2half2_rn(h0, h1);
            *(__half2*)&g_hh[(size_t)(r0 + 8) * I_DIM + col] = __floats2half2_rn(h2, h3);
        }
    }
}

// ---------------------------------------------------------------------------
// Kernel 2: down GEMM  out[t,h] = h[t,:] . w2[h,:]  (inner dim I, groups of 64)
// ---------------------------------------------------------------------------
__global__ void __launch_bounds__(512, 1) gemm_down(
    const int* __restrict__ w2q, const float* __restrict__ w2s, const float* __restrict__ w2z,
    float* __restrict__ out)
{
    extern __shared__ char smem[];
    __half* As  = (__half*)smem;                       // [128][72]
    __half* Bs  = (__half*)(smem + BM * SSTR * 2);     // [128][72]
    float*  s2s = (float*)(smem + 2 * BM * SSTR * 2);
    float*  z2s = s2s + 128;

    const int tid  = threadIdx.x;
    const int lane = tid & 31;
    const int wid  = tid >> 5;
    const int wm   = wid & 3;
    const int wn   = wid >> 2;
    const int t0   = blockIdx.x * BM;
    const int h0   = blockIdx.y * BN;

    float acc[2][4][4];
#pragma unroll
    for (int mi = 0; mi < 2; mi++)
#pragma unroll
        for (int ni = 0; ni < 4; ni++)
#pragma unroll
            for (int r = 0; r < 4; r++) acc[mi][ni][r] = 0.f;

    const int arow = wm * 32 + (lane >> 2);
    const int acol = (lane & 3) * 2;
    const int brow = wn * 32 + (lane >> 2);

    for (int kc = 0; kc < I_DIM / BK; ++kc) {   // 224 chunks
        const int k0 = kc * BK;
        if (tid < 256) {
            int r = tid & 127;
            if (tid < 128) s2s[r] = w2s[(size_t)(h0 + r) * NG2 + kc];
            else           z2s[r] = w2z[(size_t)(h0 + r) * NG2 + kc];
        }
        __syncthreads();

#pragma unroll
        for (int j = 0; j < 2; j++) {
            int v = tid + j * 512;
            int r = v >> 3, c = (v & 7) * 8;
            *(uint4*)(As + r * SSTR + c) =
                *(const uint4*)(g_hh + (size_t)(t0 + r) * I_DIM + k0 + c);
        }
#pragma unroll
        for (int j = 0; j < 4; j++) {
            int v = tid + j * 512;
            int r = v >> 4, c = (v & 15) * 4;
            int4 q = *(const int4*)(w2q + (size_t)(h0 + r) * I_DIM + k0 + c);
            float s = s2s[r], z = z2s[r];
            *(__half2*)(Bs + r * SSTR + c)     = __floats2half2_rn(((float)q.x - z) * s, ((float)q.y - z) * s);
            *(__half2*)(Bs + r * SSTR + c + 2) = __floats2half2_rn(((float)q.z - z) * s, ((float)q.w - z) * s);
        }
        __syncthreads();

#pragma unroll
        for (int ks = 0; ks < 4; ks++) {
            const int kb = ks * 16 + acol;
            uint32_t a[2][4];
#pragma unroll
            for (int mi = 0; mi < 2; mi++) {
                const __half* p = As + (arow + mi * 16) * SSTR + kb;
                a[mi][0] = *(const uint32_t*)p;
                a[mi][1] = *(const uint32_t*)(p + 8 * SSTR);
                a[mi][2] = *(const uint32_t*)(p + 8);
                a[mi][3] = *(const uint32_t*)(p + 8 * SSTR + 8);
            }
#pragma unroll
            for (int ni = 0; ni < 4; ni++) {
                const __half* pb = Bs + (brow + ni * 8) * SSTR + kb;
                uint32_t b0 = *(const uint32_t*)pb;
                uint32_t b1 = *(const uint32_t*)(pb + 8);
#pragma unroll
                for (int mi = 0; mi < 2; mi++) mma16816(acc[mi][ni], a[mi], b0, b1);
            }
        }
    }

    // Epilogue: fp32 stores
#pragma unroll
    for (int mi = 0; mi < 2; mi++) {
#pragma unroll
        for (int ni = 0; ni < 4; ni++) {
            int r0  = t0 + wm * 32 + mi * 16 + (lane >> 2);
            int col = h0 + wn * 32 + ni * 8 + (lane & 3) * 2;
            *(float2*)&out[(size_t)r0 * H_DIM + col] =
                make_float2(acc[mi][ni][0], acc[mi][ni][1]);
            *(float2*)&out[(size_t)(r0 + 8) * H_DIM + col] =
                make_float2(acc[mi][ni][2], acc[mi][ni][3]);
        }
    }
}

// ---------------------------------------------------------------------------
extern "C" void kernel_launch(void* const* d_in, const int* in_sizes, int n_in,
                              void* d_out, int out_size) {
    (void)in_sizes; (void)n_in; (void)out_size;
    const float* x   = (const float*)d_in[0];
    const int*   w1q = (const int*)  d_in[1];
    const float* w1s = (const float*)d_in[2];
    const float* w1z = (const float*)d_in[3];
    const int*   w3q = (const int*)  d_in[4];
    const float* w3s = (const float*)d_in[5];
    const float* w3z = (const float*)d_in[6];
    const int*   w2q = (const int*)  d_in[7];
    const float* w2s = (const float*)d_in[8];
    const float* w2z = (const float*)d_in[9];
    float* out = (float*)d_out;

    cudaFuncSetAttribute(gemm_gateup, cudaFuncAttributeMaxDynamicSharedMemorySize, SMEM_GU);
    cudaFuncSetAttribute(gemm_down,   cudaFuncAttributeMaxDynamicSharedMemorySize, SMEM_DN);

    cvt_x_kernel<<<(T_DIM * H_DIM) / 1024, 256>>>(x);
    gemm_gateup<<<dim3(T_DIM / BM, I_DIM / BN), 512, SMEM_GU>>>(w1q, w1s, w1z, w3q, w3s, w3z);
    gemm_down  <<<dim3(T_DIM / BM, H_DIM / BN), 512, SMEM_DN>>>(w2q, w2s, w2z, out);
}

// round 3
// speedup vs baseline: 1.3453x; 1.3453x over previous
#include <cuda_runtime.h>
#include <cuda_fp16.h>
#include <cstdint>

// Problem dims (fixed)
#define T_DIM 256
#define H_DIM 4096
#define I_DIM 14336
#define GS 64
#define NG1 (H_DIM / GS)   // 64
#define NG2 (I_DIM / GS)   // 224

#define SSTR 72            // smem row stride in halves (64 + 8 pad)

// Scratch (static __device__: allocation-free per harness rules)
__device__ __half g_xh[T_DIM * H_DIM];    // x in fp16
__device__ float  g_gate[T_DIM * I_DIM];  // raw gate (x @ w1^T), fp32
__device__ __half g_hh[T_DIM * I_DIM];    // silu(gate)*up, fp16

__device__ __forceinline__ uint32_t h2_as_u32(__half2 h) {
    union { __half2 h2; uint32_t u; } cvt;
    cvt.h2 = h;
    return cvt.u;
}

__device__ __forceinline__ unsigned smem_u32(const void* p) {
    return (unsigned)__cvta_generic_to_shared(p);
}
__device__ __forceinline__ void cp_async16(void* dst, const void* src) {
    asm volatile("cp.async.cg.shared.global [%0], [%1], 16;\n"
                 :: "r"(smem_u32(dst)), "l"(src));
}
__device__ __forceinline__ void cp_commit() { asm volatile("cp.async.commit_group;\n"); }
template<int N> __device__ __forceinline__ void cp_wait() {
    asm volatile("cp.async.wait_group %0;\n" :: "n"(N));
    __syncwarp();
}

__device__ __forceinline__ void mma16816(float* c, const uint32_t* a, uint32_t b0, uint32_t b1) {
    asm volatile(
        "mma.sync.aligned.m16n8k16.row.col.f32.f16.f16.f32 "
        "{%0,%1,%2,%3}, {%4,%5,%6,%7}, {%8,%9}, {%0,%1,%2,%3};\n"
        : "+f"(c[0]), "+f"(c[1]), "+f"(c[2]), "+f"(c[3])
        : "r"(a[0]), "r"(a[1]), "r"(a[2]), "r"(a[3]), "r"(b0), "r"(b1));
}

// ---------------------------------------------------------------------------
// Kernel 0: x [256,4096] fp32 -> fp16
// ---------------------------------------------------------------------------
__global__ void cvt_x_kernel(const float* __restrict__ x) {
    int i = (blockIdx.x * blockDim.x + threadIdx.x) * 4;
    float4 v = *(const float4*)(x + i);
    *(__half2*)&g_xh[i]     = __floats2half2_rn(v.x, v.y);
    *(__half2*)&g_xh[i + 2] = __floats2half2_rn(v.z, v.w);
}

// ---------------------------------------------------------------------------
// Projection GEMM:  acc[t,i] = x[t,:] . w[i,:]   (K = H_DIM, group = K-chunk)
// BM=128, BN=128, BK=64, 512 threads (16 warps, 4x4).
// Pipelined: A via cp.async double-buffer; B int32 via register staging
// (LDG one chunk ahead), dequant -> fp16 smem at consume time.
// EPI=0: store raw fp32 acc to g_gate.
// EPI=1: h = silu(gate)*acc -> fp16 g_hh.
// ---------------------------------------------------------------------------
template<int EPI>
__global__ void __launch_bounds__(512, 1) gemm_proj(
    const int* __restrict__ wq, const float* __restrict__ ws, const float* __restrict__ wz)
{
    extern __shared__ char smem[];
    __half* As = (__half*)smem;                          // [2][128][SSTR]
    __half* Bs = (__half*)(smem + 2 * 128 * SSTR * 2);   // [2][128][SSTR]

    const int tid  = threadIdx.x;
    const int lane = tid & 31;
    const int wid  = tid >> 5;
    const int wm   = wid & 3;
    const int wn   = wid >> 2;
    const int t0   = blockIdx.x * 128;
    const int i0   = blockIdx.y * 128;

    // B register staging: thread covers row br, k = bk..bk+15 of each chunk
    const int br = tid >> 2;
    const int bk = (tid & 3) * 16;
    const int*   wq_row = wq + (size_t)(i0 + br) * H_DIM + bk;
    const float* ws_row = ws + (size_t)(i0 + br) * NG1;
    const float* wz_row = wz + (size_t)(i0 + br) * NG1;

    int4 q[4]; float s, z;

    float acc[2][4][4];
#pragma unroll
    for (int mi = 0; mi < 2; mi++)
#pragma unroll
        for (int ni = 0; ni < 4; ni++)
#pragma unroll
            for (int r = 0; r < 4; r++) acc[mi][ni][r] = 0.f;

    const int NC = H_DIM / 64;

    // prologue
    {   // issue A chunk 0 into buf 0
#pragma unroll
        for (int j = 0; j < 2; j++) {
            int v = tid + j * 512, r = v >> 3, c = (v & 7) * 8;
            cp_async16(As + r * SSTR + c, g_xh + (size_t)(t0 + r) * H_DIM + c);
        }
        cp_commit();
        // LDG B chunk 0
#pragma unroll
        for (int j = 0; j < 4; j++) q[j] = *(const int4*)(wq_row + j * 4);
        s = ws_row[0]; z = wz_row[0];
    }

    const int arow = wm * 32 + (lane >> 2);
    const int acol = (lane & 3) * 2;
    const int brw  = wn * 32 + (lane >> 2);

    for (int kc = 0; kc < NC; kc++) {
        const int buf = kc & 1;
        if (kc + 1 < NC) {     // issue A chunk kc+1 into other buffer
#pragma unroll
            for (int j = 0; j < 2; j++) {
                int v = tid + j * 512, r = v >> 3, c = (v & 7) * 8;
                cp_async16(As + (buf ^ 1) * 128 * SSTR + r * SSTR + c,
                           g_xh + (size_t)(t0 + r) * H_DIM + (kc + 1) * 64 + c);
            }
            cp_commit();
            cp_wait<1>();      // A[kc] complete
        } else {
            cp_wait<0>();
        }

        // dequant staged B regs -> fp16 smem (2 x STS.128)
        {
            __half* bp = Bs + buf * 128 * SSTR + br * SSTR + bk;
#pragma unroll
            for (int jj = 0; jj < 2; jj++) {
                uint4 v;
                int4 qa = q[jj * 2], qb = q[jj * 2 + 1];
                v.x = h2_as_u32(__floats2half2_rn(((float)qa.x - z) * s, ((float)qa.y - z) * s));
                v.y = h2_as_u32(__floats2half2_rn(((float)qa.z - z) * s, ((float)qa.w - z) * s));
                v.z = h2_as_u32(__floats2half2_rn(((float)qb.x - z) * s, ((float)qb.y - z) * s));
                v.w = h2_as_u32(__floats2half2_rn(((float)qb.z - z) * s, ((float)qb.w - z) * s));
                *(uint4*)(bp + jj * 8) = v;
            }
        }
        __syncthreads();

        if (kc + 1 < NC) {     // LDG B chunk kc+1 (hidden under compute)
#pragma unroll
            for (int j = 0; j < 4; j++) q[j] = *(const int4*)(wq_row + (kc + 1) * 64 + j * 4);
            s = ws_row[kc + 1]; z = wz_row[kc + 1];
        }

        const __half* Ab = As + buf * 128 * SSTR;
        const __half* Bb = Bs + buf * 128 * SSTR;
#pragma unroll
        for (int ks = 0; ks < 4; ks++) {
            const int kb = ks * 16 + acol;
            uint32_t a[2][4];
#pragma unroll
            for (int mi = 0; mi < 2; mi++) {
                const __half* p = Ab + (arow + mi * 16) * SSTR + kb;
                a[mi][0] = *(const uint32_t*)p;
                a[mi][1] = *(const uint32_t*)(p + 8 * SSTR);
                a[mi][2] = *(const uint32_t*)(p + 8);
                a[mi][3] = *(const uint32_t*)(p + 8 * SSTR + 8);
            }
#pragma unroll
            for (int ni = 0; ni < 4; ni++) {
                const __half* pb = Bb + (brw + ni * 8) * SSTR + kb;
                uint32_t b0 = *(const uint32_t*)pb;
                uint32_t b1 = *(const uint32_t*)(pb + 8);
#pragma unroll
                for (int mi = 0; mi < 2; mi++) mma16816(acc[mi][ni], a[mi], b0, b1);
            }
        }
        __syncthreads();
    }

    // epilogue
#pragma unroll
    for (int mi = 0; mi < 2; mi++) {
#pragma unroll
        for (int ni = 0; ni < 4; ni++) {
            int r0  = t0 + wm * 32 + mi * 16 + (lane >> 2);
            int col = i0 + wn * 32 + ni * 8 + (lane & 3) * 2;
            if (EPI == 0) {
                *(float2*)&g_gate[(size_t)r0 * I_DIM + col] =
                    make_float2(acc[mi][ni][0], acc[mi][ni][1]);
                *(float2*)&g_gate[(size_t)(r0 + 8) * I_DIM + col] =
                    make_float2(acc[mi][ni][2], acc[mi][ni][3]);
            } else {
                float2 ga = *(const float2*)&g_gate[(size_t)r0 * I_DIM + col];
                float2 gb = *(const float2*)&g_gate[(size_t)(r0 + 8) * I_DIM + col];
                float h0 = ga.x / (1.f + __expf(-ga.x)) * acc[mi][ni][0];
                float h1 = ga.y / (1.f + __expf(-ga.y)) * acc[mi][ni][1];
                float h2 = gb.x / (1.f + __expf(-gb.x)) * acc[mi][ni][2];
                float h3 = gb.y / (1.f + __expf(-gb.y)) * acc[mi][ni][3];
                *(__half2*)&g_hh[(size_t)r0 * I_DIM + col]       = __floats2half2_rn(h0, h1);
                *(__half2*)&g_hh[(size_t)(r0 + 8) * I_DIM + col] = __floats2half2_rn(h2, h3);
            }
        }
    }
}

// ---------------------------------------------------------------------------
// Down GEMM: out[t,h] = hh[t,:] . w2[h,:]   (K = I_DIM)
// BM=128, BN=64, BK=64, 256 threads (8 warps, 4x2; warp tile 32x32).
// Same pipeline structure.
// ---------------------------------------------------------------------------
__global__ void __launch_bounds__(256, 1) gemm_down(
    const int* __restrict__ wq, const float* __restrict__ ws, const float* __restrict__ wz,
    float* __restrict__ out)
{
    extern __shared__ char smem[];
    __half* As = (__half*)smem;                          // [2][128][SSTR]
    __half* Bs = (__half*)(smem + 2 * 128 * SSTR * 2);   // [2][64][SSTR]

    const int tid  = threadIdx.x;
    const int lane = tid & 31;
    const int wid  = tid >> 5;
    const int wm   = wid & 3;
    const int wn   = wid >> 2;
    const int t0   = blockIdx.x * 128;
    const int h0   = blockIdx.y * 64;

    const int br = tid >> 2;          // 0..63
    const int bk = (tid & 3) * 16;
    const int*   wq_row = wq + (size_t)(h0 + br) * I_DIM + bk;
    const float* ws_row = ws + (size_t)(h0 + br) * NG2;
    const float* wz_row = wz + (size_t)(h0 + br) * NG2;

    int4 q[4]; float s, z;

    float acc[2][4][4];
#pragma unroll
    for (int mi = 0; mi < 2; mi++)
#pragma unroll
        for (int ni = 0; ni < 4; ni++)
#pragma unroll
            for (int r = 0; r < 4; r++) acc[mi][ni][r] = 0.f;

    const int NC = I_DIM / 64;   // 224

    {
#pragma unroll
        for (int j = 0; j < 4; j++) {
            int v = tid + j * 256, r = v >> 3, c = (v & 7) * 8;
            cp_async16(As + r * SSTR + c, g_hh + (size_t)(t0 + r) * I_DIM + c);
        }
        cp_commit();
#pragma unroll
        for (int j = 0; j < 4; j++) q[j] = *(const int4*)(wq_row + j * 4);
        s = ws_row[0]; z = wz_row[0];
    }

    const int arow = wm * 32 + (lane >> 2);
    const int acol = (lane & 3) * 2;
    const int brw  = wn * 32 + (lane >> 2);

    for (int kc = 0; kc < NC; kc++) {
        const int buf = kc & 1;
        if (kc + 1 < NC) {
#pragma unroll
            for (int j = 0; j < 4; j++) {
                int v = tid + j * 256, r = v >> 3, c = (v & 7) * 8;
                cp_async16(As + (buf ^ 1) * 128 * SSTR + r * SSTR + c,
                           g_hh + (size_t)(t0 + r) * I_DIM + (kc + 1) * 64 + c);
            }
            cp_commit();
            cp_wait<1>();
        } else {
            cp_wait<0>();
        }

        {
            __half* bp = Bs + buf * 64 * SSTR + br * SSTR + bk;
#pragma unroll
            for (int jj = 0; jj < 2; jj++) {
                uint4 v;
                int4 qa = q[jj * 2], qb = q[jj * 2 + 1];
                v.x = h2_as_u32(__floats2half2_rn(((float)qa.x - z) * s, ((float)qa.y - z) * s));
                v.y = h2_as_u32(__floats2half2_rn(((float)qa.z - z) * s, ((float)qa.w - z) * s));
                v.z = h2_as_u32(__floats2half2_rn(((float)qb.x - z) * s, ((float)qb.y - z) * s));
                v.w = h2_as_u32(__floats2half2_rn(((float)qb.z - z) * s, ((float)qb.w - z) * s));
                *(uint4*)(bp + jj * 8) = v;
            }
        }
        __syncthreads();

        if (kc + 1 < NC) {
#pragma unroll
            for (int j = 0; j < 4; j++) q[j] = *(const int4*)(wq_row + (kc + 1) * 64 + j * 4);
            s = ws_row[kc + 1]; z = wz_row[kc + 1];
        }

        const __half* Ab = As + buf * 128 * SSTR;
        const __half* Bb = Bs + buf * 64 * SSTR;
#pragma unroll
        for (int ks = 0; ks < 4; ks++) {
            const int kb = ks * 16 + acol;
            uint32_t a[2][4];
#pragma unroll
            for (int mi = 0; mi < 2; mi++) {
                const __half* p = Ab + (arow + mi * 16) * SSTR + kb;
                a[mi][0] = *(const uint32_t*)p;
                a[mi][1] = *(const uint32_t*)(p + 8 * SSTR);
                a[mi][2] = *(const uint32_t*)(p + 8);
                a[mi][3] = *(const uint32_t*)(p + 8 * SSTR + 8);
            }
#pragma unroll
            for (int ni = 0; ni < 4; ni++) {
                const __half* pb = Bb + (brw + ni * 8) * SSTR + kb;
                uint32_t b0 = *(const uint32_t*)pb;
                uint32_t b1 = *(const uint32_t*)(pb + 8);
#pragma unroll
                for (int mi = 0; mi < 2; mi++) mma16816(acc[mi][ni], a[mi], b0, b1);
            }
        }
        __syncthreads();
    }

#pragma unroll
    for (int mi = 0; mi < 2; mi++) {
#pragma unroll
        for (int ni = 0; ni < 4; ni++) {
            int r0  = t0 + wm * 32 + mi * 16 + (lane >> 2);
            int col = h0 + wn * 32 + ni * 8 + (lane & 3) * 2;
            *(float2*)&out[(size_t)r0 * H_DIM + col] =
                make_float2(acc[mi][ni][0], acc[mi][ni][1]);
            *(float2*)&out[(size_t)(r0 + 8) * H_DIM + col] =
                make_float2(acc[mi][ni][2], acc[mi][ni][3]);
        }
    }
}

// ---------------------------------------------------------------------------
#define SMEM_PROJ (4 * 128 * SSTR * 2)                     // 73.7 KB
#define SMEM_DOWN (2 * 128 * SSTR * 2 + 2 * 64 * SSTR * 2) // 55.3 KB

extern "C" void kernel_launch(void* const* d_in, const int* in_sizes, int n_in,
                              void* d_out, int out_size) {
    (void)in_sizes; (void)n_in; (void)out_size;
    const float* x   = (const float*)d_in[0];
    const int*   w1q = (const int*)  d_in[1];
    const float* w1s = (const float*)d_in[2];
    const float* w1z = (const float*)d_in[3];
    const int*   w3q = (const int*)  d_in[4];
    const float* w3s = (const float*)d_in[5];
    const float* w3z = (const float*)d_in[6];
    const int*   w2q = (const int*)  d_in[7];
    const float* w2s = (const float*)d_in[8];
    const float* w2z = (const float*)d_in[9];
    float* out = (float*)d_out;

    cudaFuncSetAttribute(gemm_proj<0>, cudaFuncAttributeMaxDynamicSharedMemorySize, SMEM_PROJ);
    cudaFuncSetAttribute(gemm_proj<1>, cudaFuncAttributeMaxDynamicSharedMemorySize, SMEM_PROJ);
    cudaFuncSetAttribute(gemm_down,    cudaFuncAttributeMaxDynamicSharedMemorySize, SMEM_DOWN);

    cvt_x_kernel<<<(T_DIM * H_DIM) / 1024, 256>>>(x);
    gemm_proj<0><<<dim3(T_DIM / 128, I_DIM / 128), 512, SMEM_PROJ>>>(w1q, w1s, w1z);
    gemm_proj<1><<<dim3(T_DIM / 128, I_DIM / 128), 512, SMEM_PROJ>>>(w3q, w3s, w3z);
    gemm_down  <<<dim3(T_DIM / 128, H_DIM / 64),   256, SMEM_DOWN>>>(w2q, w2s, w2z, out);
}

// round 5
// speedup vs baseline: 1.6286x; 1.2106x over previous
// R4 resubmit (R4 run hit a container-infra failure; kernel never executed).
#include <cuda_runtime.h>
#include <cuda_fp16.h>
#include <cstdint>

// Problem dims (fixed)
#define T_DIM 256
#define H_DIM 4096
#define I_DIM 14336
#define GS 64
#define NG1 (H_DIM / GS)   // 64
#define NG2 (I_DIM / GS)   // 224
#define KSPLIT 4
#define NC2_SPLIT (NG2 / KSPLIT)   // 56 chunks per split

#define SSTR 72            // smem row stride in halves (64 + 8 pad)

// Scratch (static __device__: allocation-free per harness rules)
__device__ __half g_xh[T_DIM * H_DIM];              // x in fp16
__device__ float  g_gate[T_DIM * I_DIM];            // raw gate fp32
__device__ float  g_up[T_DIM * I_DIM];              // raw up fp32
__device__ __half g_hh[T_DIM * I_DIM];              // silu(gate)*up fp16
__device__ float  g_part[KSPLIT][T_DIM * H_DIM];    // down-GEMM split-K partials

__device__ __forceinline__ uint32_t h2_as_u32(__half2 h) {
    union { __half2 h2; uint32_t u; } cvt; cvt.h2 = h; return cvt.u;
}
__device__ __forceinline__ unsigned smem_u32(const void* p) {
    return (unsigned)__cvta_generic_to_shared(p);
}
__device__ __forceinline__ void cp_async16(void* dst, const void* src) {
    asm volatile("cp.async.cg.shared.global [%0], [%1], 16;\n"
                 :: "r"(smem_u32(dst)), "l"(src));
}
__device__ __forceinline__ void cp_commit() { asm volatile("cp.async.commit_group;\n"); }
template<int N> __device__ __forceinline__ void cp_wait() {
    asm volatile("cp.async.wait_group %0;\n" :: "n"(N));
    __syncwarp();
}
__device__ __forceinline__ void mma16816(float* c, const uint32_t* a, uint32_t b0, uint32_t b1) {
    asm volatile(
        "mma.sync.aligned.m16n8k16.row.col.f32.f16.f16.f32 "
        "{%0,%1,%2,%3}, {%4,%5,%6,%7}, {%8,%9}, {%0,%1,%2,%3};\n"
        : "+f"(c[0]), "+f"(c[1]), "+f"(c[2]), "+f"(c[3])
        : "r"(a[0]), "r"(a[1]), "r"(a[2]), "r"(a[3]), "r"(b0), "r"(b1));
}

// ---------------------------------------------------------------------------
// Kernel 0: x fp32 -> fp16
// ---------------------------------------------------------------------------
__global__ void cvt_x_kernel(const float* __restrict__ x) {
    int i = (blockIdx.x * blockDim.x + threadIdx.x) * 4;
    float4 v = *(const float4*)(x + i);
    *(__half2*)&g_xh[i]     = __floats2half2_rn(v.x, v.y);
    *(__half2*)&g_xh[i + 2] = __floats2half2_rn(v.z, v.w);
}

// ---------------------------------------------------------------------------
// Shared GEMM core: BM=128, BN=64, BK=64, 256 threads (8 warps, 4x2).
// A fp16 from gA (row stride lda), cp.async double-buffered.
// B int32 HQQ, register-staged one chunk ahead, dequant -> fp16 smem.
// Accumulates into acc[2][4][4] (warp tile 32x32).
// ---------------------------------------------------------------------------
struct GemmCore {
    const __half* gA; int lda;
    const int* wq_row; const float* ws_row; const float* wz_row;
    int t0;
    int nchunks; int kc0;   // chunk range [kc0, kc0+nchunks)
};

__device__ __forceinline__ void gemm_core_run(const GemmCore& g, char* smem, float acc[2][4][4]) {
    __half* As = (__half*)smem;                          // [2][128][SSTR]
    __half* Bs = (__half*)(smem + 2 * 128 * SSTR * 2);   // [2][64][SSTR]

    const int tid  = threadIdx.x;
    const int lane = tid & 31;
    const int wid  = tid >> 5;
    const int wm   = wid & 3;
    const int wn   = wid >> 2;

    const int br = tid >> 2;          // 0..63
    const int bk = (tid & 3) * 16;

    int4 q[4]; float s, z;

    // prologue: A chunk 0, B chunk 0
#pragma unroll
    for (int j = 0; j < 4; j++) {
        int v = tid + j * 256, r = v >> 3, c = (v & 7) * 8;
        cp_async16(As + r * SSTR + c, g.gA + (size_t)(g.t0 + r) * g.lda + g.kc0 * 64 + c);
    }
    cp_commit();
#pragma unroll
    for (int j = 0; j < 4; j++) q[j] = *(const int4*)(g.wq_row + (size_t)g.kc0 * 64 + j * 4);
    s = g.ws_row[g.kc0]; z = g.wz_row[g.kc0];

    const int arow = wm * 32 + (lane >> 2);
    const int acol = (lane & 3) * 2;
    const int brw  = wn * 32 + (lane >> 2);

    for (int kl = 0; kl < g.nchunks; kl++) {
        const int buf = kl & 1;
        if (kl + 1 < g.nchunks) {
#pragma unroll
            for (int j = 0; j < 4; j++) {
                int v = tid + j * 256, r = v >> 3, c = (v & 7) * 8;
                cp_async16(As + (buf ^ 1) * 128 * SSTR + r * SSTR + c,
                           g.gA + (size_t)(g.t0 + r) * g.lda + (g.kc0 + kl + 1) * 64 + c);
            }
            cp_commit();
            cp_wait<1>();
        } else {
            cp_wait<0>();
        }

        // dequant staged B -> fp16 smem
        {
            __half* bp = Bs + buf * 64 * SSTR + br * SSTR + bk;
#pragma unroll
            for (int jj = 0; jj < 2; jj++) {
                uint4 v;
                int4 qa = q[jj * 2], qb = q[jj * 2 + 1];
                v.x = h2_as_u32(__floats2half2_rn(((float)qa.x - z) * s, ((float)qa.y - z) * s));
                v.y = h2_as_u32(__floats2half2_rn(((float)qa.z - z) * s, ((float)qa.w - z) * s));
                v.z = h2_as_u32(__floats2half2_rn(((float)qb.x - z) * s, ((float)qb.y - z) * s));
                v.w = h2_as_u32(__floats2half2_rn(((float)qb.z - z) * s, ((float)qb.w - z) * s));
                *(uint4*)(bp + jj * 8) = v;
            }
        }
        __syncthreads();

        if (kl + 1 < g.nchunks) {
#pragma unroll
            for (int j = 0; j < 4; j++)
                q[j] = *(const int4*)(g.wq_row + (size_t)(g.kc0 + kl + 1) * 64 + j * 4);
            s = g.ws_row[g.kc0 + kl + 1]; z = g.wz_row[g.kc0 + kl + 1];
        }

        const __half* Ab = As + buf * 128 * SSTR;
        const __half* Bb = Bs + buf * 64 * SSTR;
#pragma unroll
        for (int ks = 0; ks < 4; ks++) {
            const int kb = ks * 16 + acol;
            uint32_t a[2][4];
#pragma unroll
            for (int mi = 0; mi < 2; mi++) {
                const __half* p = Ab + (arow + mi * 16) * SSTR + kb;
                a[mi][0] = *(const uint32_t*)p;
                a[mi][1] = *(const uint32_t*)(p + 8 * SSTR);
                a[mi][2] = *(const uint32_t*)(p + 8);
                a[mi][3] = *(const uint32_t*)(p + 8 * SSTR + 8);
            }
#pragma unroll
            for (int ni = 0; ni < 4; ni++) {
                const __half* pb = Bb + (brw + ni * 8) * SSTR + kb;
                uint32_t b0 = *(const uint32_t*)pb;
                uint32_t b1 = *(const uint32_t*)(pb + 8);
#pragma unroll
                for (int mi = 0; mi < 2; mi++) mma16816(acc[mi][ni], a[mi], b0, b1);
            }
        }
        __syncthreads();
    }
}

// ---------------------------------------------------------------------------
// Projection GEMM (gate & up in one launch): z=0 -> w1 -> g_gate,
//                                            z=1 -> w3 -> g_up. Raw fp32 out.
// grid (T/128, I/64, 2)
// ---------------------------------------------------------------------------
__global__ void __launch_bounds__(256, 2) gemm_proj(
    const int* __restrict__ w1q, const float* __restrict__ w1s, const float* __restrict__ w1z,
    const int* __restrict__ w3q, const float* __restrict__ w3s, const float* __restrict__ w3z)
{
    extern __shared__ char smem[];
    const int t0 = blockIdx.x * 128;
    const int i0 = blockIdx.y * 64;
    const bool up = blockIdx.z != 0;

    const int*   wq = up ? w3q : w1q;
    const float* ws = up ? w3s : w1s;
    const float* wz = up ? w3z : w1z;
    float* outp = up ? g_up : g_gate;

    const int tid = threadIdx.x;
    const int br  = tid >> 2;

    GemmCore g;
    g.gA = g_xh; g.lda = H_DIM;
    g.wq_row = wq + (size_t)(i0 + br) * H_DIM + (tid & 3) * 16;
    g.ws_row = ws + (size_t)(i0 + br) * NG1;
    g.wz_row = wz + (size_t)(i0 + br) * NG1;
    g.t0 = t0; g.nchunks = NG1; g.kc0 = 0;

    float acc[2][4][4];
#pragma unroll
    for (int mi = 0; mi < 2; mi++)
#pragma unroll
        for (int ni = 0; ni < 4; ni++)
#pragma unroll
            for (int r = 0; r < 4; r++) acc[mi][ni][r] = 0.f;

    gemm_core_run(g, smem, acc);

    const int lane = tid & 31, wid = tid >> 5, wm = wid & 3, wn = wid >> 2;
#pragma unroll
    for (int mi = 0; mi < 2; mi++) {
#pragma unroll
        for (int ni = 0; ni < 4; ni++) {
            int r0  = t0 + wm * 32 + mi * 16 + (lane >> 2);
            int col = i0 + wn * 32 + ni * 8 + (lane & 3) * 2;
            *(float2*)&outp[(size_t)r0 * I_DIM + col] =
                make_float2(acc[mi][ni][0], acc[mi][ni][1]);
            *(float2*)&outp[(size_t)(r0 + 8) * I_DIM + col] =
                make_float2(acc[mi][ni][2], acc[mi][ni][3]);
        }
    }
}

// ---------------------------------------------------------------------------
// Activation: g_hh = silu(g_gate) * g_up  (fp16)
// ---------------------------------------------------------------------------
__global__ void act_kernel() {
    int i = (blockIdx.x * blockDim.x + threadIdx.x) * 4;
    float4 gv = *(const float4*)&g_gate[i];
    float4 uv = *(const float4*)&g_up[i];
    float h0 = gv.x / (1.f + __expf(-gv.x)) * uv.x;
    float h1 = gv.y / (1.f + __expf(-gv.y)) * uv.y;
    float h2 = gv.z / (1.f + __expf(-gv.z)) * uv.z;
    float h3 = gv.w / (1.f + __expf(-gv.w)) * uv.w;
    *(__half2*)&g_hh[i]     = __floats2half2_rn(h0, h1);
    *(__half2*)&g_hh[i + 2] = __floats2half2_rn(h2, h3);
}

// ---------------------------------------------------------------------------
// Down GEMM, split-K=4: partials into g_part[z]. grid (T/128, H/64, 4)
// ---------------------------------------------------------------------------
__global__ void __launch_bounds__(256, 2) gemm_down(
    const int* __restrict__ wq, const float* __restrict__ ws, const float* __restrict__ wz)
{
    extern __shared__ char smem[];
    const int t0  = blockIdx.x * 128;
    const int h0  = blockIdx.y * 64;
    const int spl = blockIdx.z;

    const int tid = threadIdx.x;
    const int br  = tid >> 2;

    GemmCore g;
    g.gA = g_hh; g.lda = I_DIM;
    g.wq_row = wq + (size_t)(h0 + br) * I_DIM + (tid & 3) * 16;
    g.ws_row = ws + (size_t)(h0 + br) * NG2;
    g.wz_row = wz + (size_t)(h0 + br) * NG2;
    g.t0 = t0; g.nchunks = NC2_SPLIT; g.kc0 = spl * NC2_SPLIT;

    float acc[2][4][4];
#pragma unroll
    for (int mi = 0; mi < 2; mi++)
#pragma unroll
        for (int ni = 0; ni < 4; ni++)
#pragma unroll
            for (int r = 0; r < 4; r++) acc[mi][ni][r] = 0.f;

    gemm_core_run(g, smem, acc);

    const int lane = tid & 31, wid = tid >> 5, wm = wid & 3, wn = wid >> 2;
    float* outp = g_part[spl];
#pragma unroll
    for (int mi = 0; mi < 2; mi++) {
#pragma unroll
        for (int ni = 0; ni < 4; ni++) {
            int r0  = t0 + wm * 32 + mi * 16 + (lane >> 2);
            int col = h0 + wn * 32 + ni * 8 + (lane & 3) * 2;
            *(float2*)&outp[(size_t)r0 * H_DIM + col] =
                make_float2(acc[mi][ni][0], acc[mi][ni][1]);
            *(float2*)&outp[(size_t)(r0 + 8) * H_DIM + col] =
                make_float2(acc[mi][ni][2], acc[mi][ni][3]);
        }
    }
}

// ---------------------------------------------------------------------------
// Reduce split-K partials -> out
// ---------------------------------------------------------------------------
__global__ void reduce_kernel(float* __restrict__ out) {
    int i = (blockIdx.x * blockDim.x + threadIdx.x) * 4;
    float4 a = *(const float4*)&g_part[0][i];
    float4 b = *(const float4*)&g_part[1][i];
    float4 c = *(const float4*)&g_part[2][i];
    float4 d = *(const float4*)&g_part[3][i];
    float4 r;
    r.x = (a.x + b.x) + (c.x + d.x);
    r.y = (a.y + b.y) + (c.y + d.y);
    r.z = (a.z + b.z) + (c.z + d.z);
    r.w = (a.w + b.w) + (c.w + d.w);
    *(float4*)&out[i] = r;
}

// ---------------------------------------------------------------------------
#define SMEM_GEMM (2 * 128 * SSTR * 2 + 2 * 64 * SSTR * 2)   // 55.3 KB

extern "C" void kernel_launch(void* const* d_in, const int* in_sizes, int n_in,
                              void* d_out, int out_size) {
    (void)in_sizes; (void)n_in; (void)out_size;
    const float* x   = (const float*)d_in[0];
    const int*   w1q = (const int*)  d_in[1];
    const float* w1s = (const float*)d_in[2];
    const float* w1z = (const float*)d_in[3];
    const int*   w3q = (const int*)  d_in[4];
    const float* w3s = (const float*)d_in[5];
    const float* w3z = (const float*)d_in[6];
    const int*   w2q = (const int*)  d_in[7];
    const float* w2s = (const float*)d_in[8];
    const float* w2z = (const float*)d_in[9];
    float* out = (float*)d_out;

    cudaFuncSetAttribute(gemm_proj, cudaFuncAttributeMaxDynamicSharedMemorySize, SMEM_GEMM);
    cudaFuncSetAttribute(gemm_down, cudaFuncAttributeMaxDynamicSharedMemorySize, SMEM_GEMM);

    cvt_x_kernel<<<(T_DIM * H_DIM) / 1024, 256>>>(x);
    gemm_proj<<<dim3(T_DIM / 128, I_DIM / 64, 2), 256, SMEM_GEMM>>>(w1q, w1s, w1z, w3q, w3s, w3z);
    act_kernel<<<(T_DIM * I_DIM) / 1024, 256>>>();
    gemm_down<<<dim3(T_DIM / 128, H_DIM / 64, KSPLIT), 256, SMEM_GEMM>>>(w2q, w2s, w2z);
    reduce_kernel<<<(T_DIM * H_DIM) / 1024, 256>>>(out);
}

// round 7
// speedup vs baseline: 1.8376x; 1.1283x over previous
#include <cuda_runtime.h>
#include <cuda_fp16.h>
#include <cstdint>

// Problem dims (fixed)
#define T_DIM 256
#define H_DIM 4096
#define I_DIM 14336
#define GS 64
#define NG1 (H_DIM / GS)   // 64
#define NG2 (I_DIM / GS)   // 224
#define KSPLIT 4
#define NC2_SPLIT (NG2 / KSPLIT)   // 56 chunks per split

#define SSTR 72            // smem row stride in halves (64 + 8 pad)

// Scratch (static __device__: allocation-free per harness rules)
__device__ __half g_xh[T_DIM * H_DIM];              // x in fp16
__device__ float  g_gate[T_DIM * I_DIM];            // raw gate fp32
__device__ float  g_up[T_DIM * I_DIM];              // raw up fp32
__device__ __half g_hh[T_DIM * I_DIM];              // silu(gate)*up fp16
__device__ float  g_part[KSPLIT][T_DIM * H_DIM];    // down-GEMM split-K partials

__device__ __forceinline__ uint32_t h2_as_u32(__half2 h) {
    union { __half2 h2; uint32_t u; } cvt; cvt.h2 = h; return cvt.u;
}
__device__ __forceinline__ unsigned smem_u32(const void* p) {
    return (unsigned)__cvta_generic_to_shared(p);
}
__device__ __forceinline__ void cp_async16(void* dst, const void* src) {
    asm volatile("cp.async.cg.shared.global [%0], [%1], 16;\n"
                 :: "r"(smem_u32(dst)), "l"(src));
}
__device__ __forceinline__ void cp_commit() { asm volatile("cp.async.commit_group;\n"); }
template<int N> __device__ __forceinline__ void cp_wait() {
    asm volatile("cp.async.wait_group %0;\n" :: "n"(N));
    __syncwarp();
}
__device__ __forceinline__ void mma16816(float* c, const uint32_t* a, uint32_t b0, uint32_t b1) {
    asm volatile(
        "mma.sync.aligned.m16n8k16.row.col.f32.f16.f16.f32 "
        "{%0,%1,%2,%3}, {%4,%5,%6,%7}, {%8,%9}, {%0,%1,%2,%3};\n"
        : "+f"(c[0]), "+f"(c[1]), "+f"(c[2]), "+f"(c[3])
        : "r"(a[0]), "r"(a[1]), "r"(a[2]), "r"(a[3]), "r"(b0), "r"(b1));
}
__device__ __forceinline__ void ldsm4(uint32_t* r, uint32_t addr) {
    asm volatile("ldmatrix.sync.aligned.m8n8.x4.shared.b16 {%0,%1,%2,%3}, [%4];"
                 : "=r"(r[0]), "=r"(r[1]), "=r"(r[2]), "=r"(r[3]) : "r"(addr));
}

// ---------------------------------------------------------------------------
// Kernel 0: x fp32 -> fp16
// ---------------------------------------------------------------------------
__global__ void cvt_x_kernel(const float* __restrict__ x) {
    int i = (blockIdx.x * blockDim.x + threadIdx.x) * 4;
    float4 v = *(const float4*)(x + i);
    *(__half2*)&g_xh[i]     = __floats2half2_rn(v.x, v.y);
    *(__half2*)&g_xh[i + 2] = __floats2half2_rn(v.z, v.w);
}

// ---------------------------------------------------------------------------
// Shared GEMM core: BM=128, BN=64, BK=64, 256 threads (8 warps, 4x2).
// A fp16 from gA (cp.async double-buffered); B int32 HQQ register-staged one
// chunk ahead, dequant -> fp16 smem. Fragments via ldmatrix.x4.
// ---------------------------------------------------------------------------
struct GemmCore {
    const __half* gA; int lda;
    const int* wq_row; const float* ws_row; const float* wz_row;
    int t0;
    int nchunks; int kc0;   // chunk range [kc0, kc0+nchunks)
};

__device__ __forceinline__ void gemm_core_run(const GemmCore& g, char* smem, float acc[2][4][4]) {
    __half* As = (__half*)smem;                          // [2][128][SSTR]
    __half* Bs = (__half*)(smem + 2 * 128 * SSTR * 2);   // [2][64][SSTR]

    const int tid  = threadIdx.x;
    const int lane = tid & 31;
    const int wid  = tid >> 5;
    const int wm   = wid & 3;
    const int wn   = wid >> 2;

    const int br = tid >> 2;          // 0..63
    const int bk = (tid & 3) * 16;

    int4 q[4]; float s, z;

    // prologue: A chunk 0, B chunk 0
#pragma unroll
    for (int j = 0; j < 4; j++) {
        int v = tid + j * 256, r = v >> 3, c = (v & 7) * 8;
        cp_async16(As + r * SSTR + c, g.gA + (size_t)(g.t0 + r) * g.lda + g.kc0 * 64 + c);
    }
    cp_commit();
#pragma unroll
    for (int j = 0; j < 4; j++) q[j] = *(const int4*)(g.wq_row + (size_t)g.kc0 * 64 + j * 4);
    s = g.ws_row[g.kc0]; z = g.wz_row[g.kc0];

    // ldmatrix per-lane addresses (bytes): row = tile_row + lane%16, col8 = lane/16
    const int lrow = lane & 15, lcol = lane >> 4;
    const uint32_t As_u = smem_u32(As);
    const uint32_t Bs_u = smem_u32(Bs);
    uint32_t a_addr[2], b_addr[2];
#pragma unroll
    for (int mi = 0; mi < 2; mi++)
        a_addr[mi] = As_u + ((wm * 32 + mi * 16 + lrow) * SSTR + lcol * 8) * 2;
#pragma unroll
    for (int nj = 0; nj < 2; nj++)
        b_addr[nj] = Bs_u + ((wn * 32 + nj * 16 + lrow) * SSTR + lcol * 8) * 2;

    for (int kl = 0; kl < g.nchunks; kl++) {
        const int buf = kl & 1;
        if (kl + 1 < g.nchunks) {
#pragma unroll
            for (int j = 0; j < 4; j++) {
                int v = tid + j * 256, r = v >> 3, c = (v & 7) * 8;
                cp_async16(As + (buf ^ 1) * 128 * SSTR + r * SSTR + c,
                           g.gA + (size_t)(g.t0 + r) * g.lda + (g.kc0 + kl + 1) * 64 + c);
            }
            cp_commit();
            cp_wait<1>();
        } else {
            cp_wait<0>();
        }

        // dequant staged B -> fp16 smem
        {
            __half* bp = Bs + buf * 64 * SSTR + br * SSTR + bk;
#pragma unroll
            for (int jj = 0; jj < 2; jj++) {
                uint4 v;
                int4 qa = q[jj * 2], qb = q[jj * 2 + 1];
                v.x = h2_as_u32(__floats2half2_rn(((float)qa.x - z) * s, ((float)qa.y - z) * s));
                v.y = h2_as_u32(__floats2half2_rn(((float)qa.z - z) * s, ((float)qa.w - z) * s));
                v.z = h2_as_u32(__floats2half2_rn(((float)qb.x - z) * s, ((float)qb.y - z) * s));
                v.w = h2_as_u32(__floats2half2_rn(((float)qb.z - z) * s, ((float)qb.w - z) * s));
                *(uint4*)(bp + jj * 8) = v;
            }
        }
        __syncthreads();

        if (kl + 1 < g.nchunks) {
#pragma unroll
            for (int j = 0; j < 4; j++)
                q[j] = *(const int4*)(g.wq_row + (size_t)(g.kc0 + kl + 1) * 64 + j * 4);
            s = g.ws_row[g.kc0 + kl + 1]; z = g.wz_row[g.kc0 + kl + 1];
        }

        const uint32_t abuf = buf * 128 * SSTR * 2;
        const uint32_t bbuf = buf * 64 * SSTR * 2;
#pragma unroll
        for (int ks = 0; ks < 4; ks++) {
            const uint32_t ko = ks * 32;   // 16 halves per k-step
            uint32_t af[2][4], bf[2][4];
            ldsm4(af[0], a_addr[0] + abuf + ko);
            ldsm4(af[1], a_addr[1] + abuf + ko);
            ldsm4(bf[0], b_addr[0] + bbuf + ko);
            ldsm4(bf[1], b_addr[1] + bbuf + ko);
            // B x4 over n16: m0=n0-7/k0-7, m1=n8-15/k0-7, m2=n0-7/k8-15, m3=n8-15/k8-15
#pragma unroll
            for (int mi = 0; mi < 2; mi++) {
                mma16816(acc[mi][0], af[mi], bf[0][0], bf[0][2]);
                mma16816(acc[mi][1], af[mi], bf[0][1], bf[0][3]);
                mma16816(acc[mi][2], af[mi], bf[1][0], bf[1][2]);
                mma16816(acc[mi][3], af[mi], bf[1][1], bf[1][3]);
            }
        }
        __syncthreads();
    }
}

// ---------------------------------------------------------------------------
// Projection GEMM (gate & up in one launch): z=0 -> w1 -> g_gate,
//                                            z=1 -> w3 -> g_up. Raw fp32 out.
// grid (T/128, I/64, 2)
// ---------------------------------------------------------------------------
__global__ void __launch_bounds__(256, 2) gemm_proj(
    const int* __restrict__ w1q, const float* __restrict__ w1s, const float* __restrict__ w1z,
    const int* __restrict__ w3q, const float* __restrict__ w3s, const float* __restrict__ w3z)
{
    extern __shared__ char smem[];
    const int t0 = blockIdx.x * 128;
    const int i0 = blockIdx.y * 64;
    const bool up = blockIdx.z != 0;

    const int*   wq = up ? w3q : w1q;
    const float* ws = up ? w3s : w1s;
    const float* wz = up ? w3z : w1z;
    float* outp = up ? g_up : g_gate;

    const int tid = threadIdx.x;
    const int br  = tid >> 2;

    GemmCore g;
    g.gA = g_xh; g.lda = H_DIM;
    g.wq_row = wq + (size_t)(i0 + br) * H_DIM + (tid & 3) * 16;
    g.ws_row = ws + (size_t)(i0 + br) * NG1;
    g.wz_row = wz + (size_t)(i0 + br) * NG1;
    g.t0 = t0; g.nchunks = NG1; g.kc0 = 0;

    float acc[2][4][4];
#pragma unroll
    for (int mi = 0; mi < 2; mi++)
#pragma unroll
        for (int ni = 0; ni < 4; ni++)
#pragma unroll
            for (int r = 0; r < 4; r++) acc[mi][ni][r] = 0.f;

    gemm_core_run(g, smem, acc);

    const int lane = tid & 31, wid = tid >> 5, wm = wid & 3, wn = wid >> 2;
#pragma unroll
    for (int mi = 0; mi < 2; mi++) {
#pragma unroll
        for (int ni = 0; ni < 4; ni++) {
            int r0  = t0 + wm * 32 + mi * 16 + (lane >> 2);
            int col = i0 + wn * 32 + ni * 8 + (lane & 3) * 2;
            *(float2*)&outp[(size_t)r0 * I_DIM + col] =
                make_float2(acc[mi][ni][0], acc[mi][ni][1]);
            *(float2*)&outp[(size_t)(r0 + 8) * I_DIM + col] =
                make_float2(acc[mi][ni][2], acc[mi][ni][3]);
        }
    }
}

// ---------------------------------------------------------------------------
// Activation: g_hh = silu(g_gate) * g_up  (fp16)
// ---------------------------------------------------------------------------
__global__ void act_kernel() {
    int i = (blockIdx.x * blockDim.x + threadIdx.x) * 4;
    float4 gv = *(const float4*)&g_gate[i];
    float4 uv = *(const float4*)&g_up[i];
    float h0 = gv.x / (1.f + __expf(-gv.x)) * uv.x;
    float h1 = gv.y / (1.f + __expf(-gv.y)) * uv.y;
    float h2 = gv.z / (1.f + __expf(-gv.z)) * uv.z;
    float h3 = gv.w / (1.f + __expf(-gv.w)) * uv.w;
    *(__half2*)&g_hh[i]     = __floats2half2_rn(h0, h1);
    *(__half2*)&g_hh[i + 2] = __floats2half2_rn(h2, h3);
}

// ---------------------------------------------------------------------------
// Down GEMM, split-K=4: partials into g_part[z]. grid (T/128, H/64, 4)
// ---------------------------------------------------------------------------
__global__ void __launch_bounds__(256, 2) gemm_down(
    const int* __restrict__ wq, const float* __restrict__ ws, const float* __restrict__ wz)
{
    extern __shared__ char smem[];
    const int t0  = blockIdx.x * 128;
    const int h0  = blockIdx.y * 64;
    const int spl = blockIdx.z;

    const int tid = threadIdx.x;
    const int br  = tid >> 2;

    GemmCore g;
    g.gA = g_hh; g.lda = I_DIM;
    g.wq_row = wq + (size_t)(h0 + br) * I_DIM + (tid & 3) * 16;
    g.ws_row = ws + (size_t)(h0 + br) * NG2;
    g.wz_row = wz + (size_t)(h0 + br) * NG2;
    g.t0 = t0; g.nchunks = NC2_SPLIT; g.kc0 = spl * NC2_SPLIT;

    float acc[2][4][4];
#pragma unroll
    for (int mi = 0; mi < 2; mi++)
#pragma unroll
        for (int ni = 0; ni < 4; ni++)
#pragma unroll
            for (int r = 0; r < 4; r++) acc[mi][ni][r] = 0.f;

    gemm_core_run(g, smem, acc);

    const int lane = tid & 31, wid = tid >> 5, wm = wid & 3, wn = wid >> 2;
    float* outp = g_part[spl];
#pragma unroll
    for (int mi = 0; mi < 2; mi++) {
#pragma unroll
        for (int ni = 0; ni < 4; ni++) {
            int r0  = t0 + wm * 32 + mi * 16 + (lane >> 2);
            int col = h0 + wn * 32 + ni * 8 + (lane & 3) * 2;
            *(float2*)&outp[(size_t)r0 * H_DIM + col] =
                make_float2(acc[mi][ni][0], acc[mi][ni][1]);
            *(float2*)&outp[(size_t)(r0 + 8) * H_DIM + col] =
                make_float2(acc[mi][ni][2], acc[mi][ni][3]);
        }
    }
}

// ---------------------------------------------------------------------------
// Reduce split-K partials -> out
// ---------------------------------------------------------------------------
__global__ void reduce_kernel(float* __restrict__ out) {
    int i = (blockIdx.x * blockDim.x + threadIdx.x) * 4;
    float4 a = *(const float4*)&g_part[0][i];
    float4 b = *(const float4*)&g_part[1][i];
    float4 c = *(const float4*)&g_part[2][i];
    float4 d = *(const float4*)&g_part[3][i];
    float4 r;
    r.x = (a.x + b.x) + (c.x + d.x);
    r.y = (a.y + b.y) + (c.y + d.y);
    r.z = (a.z + b.z) + (c.z + d.z);
    r.w = (a.w + b.w) + (c.w + d.w);
    *(float4*)&out[i] = r;
}

// ---------------------------------------------------------------------------
#define SMEM_GEMM (2 * 128 * SSTR * 2 + 2 * 64 * SSTR * 2)   // 55.3 KB

extern "C" void kernel_launch(void* const* d_in, const int* in_sizes, int n_in,
                              void* d_out, int out_size) {
    (void)in_sizes; (void)n_in; (void)out_size;
    const float* x   = (const float*)d_in[0];
    const int*   w1q = (const int*)  d_in[1];
    const float* w1s = (const float*)d_in[2];
    const float* w1z = (const float*)d_in[3];
    const int*   w3q = (const int*)  d_in[4];
    const float* w3s = (const float*)d_in[5];
    const float* w3z = (const float*)d_in[6];
    const int*   w2q = (const int*)  d_in[7];
    const float* w2s = (const float*)d_in[8];
    const float* w2z = (const float*)d_in[9];
    float* out = (float*)d_out;

    cudaFuncSetAttribute(gemm_proj, cudaFuncAttributeMaxDynamicSharedMemorySize, SMEM_GEMM);
    cudaFuncSetAttribute(gemm_down, cudaFuncAttributeMaxDynamicSharedMemorySize, SMEM_GEMM);

    cvt_x_kernel<<<(T_DIM * H_DIM) / 1024, 256>>>(x);
    gemm_proj<<<dim3(T_DIM / 128, I_DIM / 64, 2), 256, SMEM_GEMM>>>(w1q, w1s, w1z, w3q, w3s, w3z);
    act_kernel<<<(T_DIM * I_DIM) / 1024, 256>>>();
    gemm_down<<<dim3(T_DIM / 128, H_DIM / 64, KSPLIT), 256, SMEM_GEMM>>>(w2q, w2s, w2z);
    reduce_kernel<<<(T_DIM * H_DIM) / 1024, 256>>>(out);
}